// round 11
// baseline (speedup 1.0000x reference)
#include <cuda_runtime.h>
#include <cuda_fp16.h>
#include <math.h>
#include <stdint.h>

// ---------------------------------------------------------------------------
// Problem constants
// ---------------------------------------------------------------------------
#define N_VOTERS   1048576
#define N_SEG      4096
#define EMB        128
#define TILE       128                     // voters per tile
#define NT         (N_VOTERS / TILE)       // 8192 tiles
#define XS         40                      // row stride (halves) for K=32 bufs
#define HS         136                     // row stride (halves) for K=128 bufs
#define HPAD       132

// zero-initialized at module load; every execution re-zeroes it in global_kernel
__device__ float g_agg[N_SEG * EMB];

// ---------------------------------------------------------------------------
// SMEM layout (byte offsets, 16B aligned). Two tile groups (g = 0,1).
// ---------------------------------------------------------------------------
#define SM_W1    0        // [128][XS] half : 10240
#define SM_W2    10240    // [128][HS] half : 34816
#define SM_W3    45056    // [128][HS] half : 34816
#define SM_XS    79872    // 2 x [128][XS] half : 20480
#define SM_H     100352   // 2 x [128][HS] half : 69632
#define SM_B3    169984   // f32 bias3 : 512
#define SM_IDX   170496   // 2 x 128 int : 1024
#define SM_HB1   171520   // half2 bias1 : 256
#define SM_HB2   171776   // half2 bias2 : 256
#define SM_XST   172032   // 2 x [128][32] f32 x-stage : 32768
#define SM_IST   204800   // 2 x 128 int idx-stage : 1024
#define SM_SZ    205824

static __device__ __forceinline__ uint32_t s2u(const void* p) {
    uint32_t a;
    asm("{ .reg .u64 t; cvta.to.shared.u64 t, %1; cvt.u32.u64 %0, t; }" : "=r"(a) : "l"(p));
    return a;
}

static __device__ __forceinline__ void ldsm4(uint32_t* r, uint32_t addr) {
    asm volatile("ldmatrix.sync.aligned.m8n8.x4.shared.b16 {%0,%1,%2,%3}, [%4];"
                 : "=r"(r[0]), "=r"(r[1]), "=r"(r[2]), "=r"(r[3]) : "r"(addr));
}

static __device__ __forceinline__ void stsm4(uint32_t addr, uint32_t r0, uint32_t r1,
                                             uint32_t r2, uint32_t r3) {
    asm volatile("stmatrix.sync.aligned.m8n8.x4.shared.b16 [%0], {%1,%2,%3,%4};"
                 :: "r"(addr), "r"(r0), "r"(r1), "r"(r2), "r"(r3) : "memory");
}

static __device__ __forceinline__ void mma16816_f32(float* d, const uint32_t* a,
                                                    uint32_t b0, uint32_t b1) {
    asm volatile("mma.sync.aligned.m16n8k16.row.col.f32.f16.f16.f32 "
                 "{%0,%1,%2,%3}, {%4,%5,%6,%7}, {%8,%9}, {%0,%1,%2,%3};"
                 : "+f"(d[0]), "+f"(d[1]), "+f"(d[2]), "+f"(d[3])
                 : "r"(a[0]), "r"(a[1]), "r"(a[2]), "r"(a[3]), "r"(b0), "r"(b1));
}

static __device__ __forceinline__ void mma16816_f16(uint32_t* d, const uint32_t* a,
                                                    uint32_t b0, uint32_t b1) {
    asm volatile("mma.sync.aligned.m16n8k16.row.col.f16.f16.f16.f16 "
                 "{%0,%1}, {%2,%3,%4,%5}, {%6,%7}, {%0,%1};"
                 : "+r"(d[0]), "+r"(d[1])
                 : "r"(a[0]), "r"(a[1]), "r"(a[2]), "r"(a[3]), "r"(b0), "r"(b1));
}

#define CP_ASYNC16(dst, src) asm volatile("cp.async.cg.shared.global [%0], [%1], 16;" :: "r"(dst), "l"(src) : "memory")
#define CP_ASYNC4(dst, src)  asm volatile("cp.async.ca.shared.global [%0], [%1], 4;"  :: "r"(dst), "l"(src) : "memory")
#define CP_COMMIT()          asm volatile("cp.async.commit_group;" ::: "memory")
#define CP_WAIT0()           asm volatile("cp.async.wait_group 0;" ::: "memory")

// ---------------------------------------------------------------------------
// fp16-accumulating layer (layers 1 & 2): ReLU, stmatrix out (stride HS)
// ---------------------------------------------------------------------------
template<int KCH, int STA, int STB>
static __device__ __forceinline__ void layer_h16(uint32_t aAddr, uint32_t bAddr,
                                                 const __half2* __restrict__ hbias,
                                                 uint32_t outAddr, int lane)
{
    const int l7 = lane & 7, lq = (lane >> 3) & 1, lh = lane >> 4;
    const uint32_t aRow = aAddr + (uint32_t)((l7 + lq * 8) * STA) * 2u + (uint32_t)lh * 16u;
    const uint32_t bRow = bAddr + (uint32_t)((l7 + lh * 8) * STB) * 2u + (uint32_t)lq * 16u;

    uint32_t d[16][2];
    #pragma unroll
    for (int n = 0; n < 16; ++n) { d[n][0] = 0u; d[n][1] = 0u; }

    #pragma unroll
    for (int kc = 0; kc < KCH; ++kc) {
        uint32_t a[4];
        ldsm4(a, aRow + (uint32_t)kc * 32u);
        #pragma unroll
        for (int p = 0; p < 8; ++p) {
            uint32_t b[4];
            ldsm4(b, bRow + (uint32_t)p * (32u * STB) + (uint32_t)kc * 32u);
            mma16816_f16(d[2 * p],     a, b[0], b[1]);
            mma16816_f16(d[2 * p + 1], a, b[2], b[3]);
        }
    }

    // epilogue: bias + ReLU on fragments, then stmatrix.x4 per n-pair
    const int cq = 2 * (lane & 3);
    const __half2 z = __float2half2_rn(0.0f);
    const uint32_t stBase = outAddr + ((uint32_t)((lane & 15) * HS) + (uint32_t)((lane >> 4) * 8)) * 2u;
    #pragma unroll
    for (int p = 0; p < 8; ++p) {
        const int n0 = 2 * p, n1 = 2 * p + 1;
        __half2 hb0 = hbias[(n0 * 8 + cq) >> 1];
        __half2 hb1 = hbias[(n1 * 8 + cq) >> 1];
        __half2 v00 = __hmax2(__hadd2(*(__half2*)&d[n0][0], hb0), z);
        __half2 v01 = __hmax2(__hadd2(*(__half2*)&d[n0][1], hb0), z);
        __half2 v10 = __hmax2(__hadd2(*(__half2*)&d[n1][0], hb1), z);
        __half2 v11 = __hmax2(__hadd2(*(__half2*)&d[n1][1], hb1), z);
        stsm4(stBase + (uint32_t)p * 32u,
              *(uint32_t*)&v00, *(uint32_t*)&v01, *(uint32_t*)&v10, *(uint32_t*)&v11);
    }
}

// ---------------------------------------------------------------------------
// fp32-accumulating layer (layer 3): no ReLU, stmatrix fp16 out (stride HS)
// ---------------------------------------------------------------------------
template<int KCH, int STA, int STB>
static __device__ __forceinline__ void layer_f32(uint32_t aAddr, uint32_t bAddr,
                                                 const float* __restrict__ bias,
                                                 uint32_t outAddr, int lane)
{
    const int l7 = lane & 7, lq = (lane >> 3) & 1, lh = lane >> 4;
    const uint32_t aRow = aAddr + (uint32_t)((l7 + lq * 8) * STA) * 2u + (uint32_t)lh * 16u;
    const uint32_t bRow = bAddr + (uint32_t)((l7 + lh * 8) * STB) * 2u + (uint32_t)lq * 16u;

    float d[16][4];
    #pragma unroll
    for (int n = 0; n < 16; ++n)
        #pragma unroll
        for (int j = 0; j < 4; ++j) d[n][j] = 0.0f;

    #pragma unroll
    for (int kc = 0; kc < KCH; ++kc) {
        uint32_t a[4];
        ldsm4(a, aRow + (uint32_t)kc * 32u);
        #pragma unroll
        for (int p = 0; p < 8; ++p) {
            uint32_t b[4];
            ldsm4(b, bRow + (uint32_t)p * (32u * STB) + (uint32_t)kc * 32u);
            mma16816_f32(d[2 * p],     a, b[0], b[1]);
            mma16816_f32(d[2 * p + 1], a, b[2], b[3]);
        }
    }

    const int cq = 2 * (lane & 3);
    const uint32_t stBase = outAddr + ((uint32_t)((lane & 15) * HS) + (uint32_t)((lane >> 4) * 8)) * 2u;
    #pragma unroll
    for (int p = 0; p < 8; ++p) {
        const int n0 = 2 * p, n1 = 2 * p + 1;
        const int c0 = n0 * 8 + cq, c1 = n1 * 8 + cq;
        __half2 v00 = __floats2half2_rn(d[n0][0] + bias[c0], d[n0][1] + bias[c0 + 1]);
        __half2 v01 = __floats2half2_rn(d[n0][2] + bias[c0], d[n0][3] + bias[c0 + 1]);
        __half2 v10 = __floats2half2_rn(d[n1][0] + bias[c1], d[n1][1] + bias[c1 + 1]);
        __half2 v11 = __floats2half2_rn(d[n1][2] + bias[c1], d[n1][3] + bias[c1 + 1]);
        stsm4(stBase + (uint32_t)p * 32u,
              *(uint32_t*)&v00, *(uint32_t*)&v01, *(uint32_t*)&v10, *(uint32_t*)&v11);
    }
}

// ---------------------------------------------------------------------------
// Kernel 1: fp16 mma.sync local MLP + sorted segment-sum.
// 512 threads = two independent 8-warp tile groups; cp.async x/idx prefetch.
// ---------------------------------------------------------------------------
__global__ __launch_bounds__(512, 1)
void local_mma(const float* __restrict__ x,
               const int* __restrict__ index,
               const float* __restrict__ lW1, const float* __restrict__ lb1,
               const float* __restrict__ lW2, const float* __restrict__ lb2,
               const float* __restrict__ lW3, const float* __restrict__ lb3)
{
    extern __shared__ __align__(1024) char sm[];
    const uint32_t sb = s2u(sm);
    const int t    = threadIdx.x;
    const int lane = t & 31;
    const int g    = t >> 8;          // tile group 0/1
    const int tg   = t & 255;         // thread id within group
    const int wl   = (t >> 5) & 7;    // warp within group

    __half*  W1t = (__half*)(sm + SM_W1);
    __half*  W2t = (__half*)(sm + SM_W2);
    __half*  W3t = (__half*)(sm + SM_W3);
    float*   fb3 = (float*)(sm + SM_B3);
    __half2* hb1 = (__half2*)(sm + SM_HB1);
    __half2* hb2 = (__half2*)(sm + SM_HB2);

    // one-time: transpose + fp16-convert weights ([k][n] gmem -> [n][k] smem)
    for (int i = t; i < 32 * 128; i += 512) {
        int k = i >> 7, n = i & 127;
        W1t[n * XS + k] = __float2half_rn(lW1[i]);
    }
    for (int i = t; i < 128 * 128; i += 512) {
        int k = i >> 7, n = i & 127;
        W2t[n * HS + k] = __float2half_rn(lW2[i]);
        W3t[n * HS + k] = __float2half_rn(lW3[i]);
    }
    if (t < 128) fb3[t] = lb3[t];
    if (t < 64) {
        hb1[t] = __floats2half2_rn(lb1[2 * t], lb1[2 * t + 1]);
        hb2[t] = __floats2half2_rn(lb2[2 * t], lb2[2 * t + 1]);
    }
    __syncthreads();

    const uint32_t xsG  = sb + SM_XS  + (uint32_t)g * 10240u;
    const uint32_t hG   = sb + SM_H   + (uint32_t)g * 34816u;
    const uint32_t xstG = sb + SM_XST + (uint32_t)g * 16384u;
    const uint32_t istG = sb + SM_IST + (uint32_t)g * 512u;
    const uint32_t xsW  = xsG + (uint32_t)(16 * wl * XS) * 2u;
    const uint32_t hW   = hG  + (uint32_t)(16 * wl * HS) * 2u;
    const uint32_t w1A  = sb + SM_W1;
    const uint32_t w2A  = sb + SM_W2;
    const uint32_t w3A  = sb + SM_W3;
    int*          idxG  = (int*)(sm + SM_IDX + g * 512);
    const int*   istRd  = (const int*)(sm + SM_IST + g * 512);
    const float* xstRd  = (const float*)(sm + SM_XST + g * 16384);
    const __half* hRd   = (const __half*)(sm + (SM_H + g * 34816));
    const int    barid  = 1 + g;
    const int    stride2 = gridDim.x * 2;

    // thread's 4 fixed 16B chunks in the stage (same for prefetch & convert)
    int prow[4], pc4[4];
    #pragma unroll
    for (int j = 0; j < 4; ++j) {
        int f = lane + 32 * j;
        prow[j] = 16 * wl + (f >> 3);
        pc4[j]  = f & 7;
    }

    int tile = blockIdx.x * 2 + g;

    // prologue prefetch
    if (tile < NT) {
        const int r0n = tile * TILE;
        #pragma unroll
        for (int j = 0; j < 4; ++j)
            CP_ASYNC16(xstG + (uint32_t)(prow[j] * 32 + pc4[j] * 4) * 4u,
                       &x[(size_t)(r0n + prow[j]) * 32 + pc4[j] * 4]);
        if (tg < 128) CP_ASYNC4(istG + (uint32_t)tg * 4u, &index[r0n + tg]);
    }
    CP_COMMIT();

    for (; tile < NT; tile += stride2) {
        CP_WAIT0();

        // convert own staged bytes: f32 stage -> fp16 xs
        #pragma unroll
        for (int j = 0; j < 4; ++j) {
            float4 v = *(const float4*)&xstRd[prow[j] * 32 + pc4[j] * 4];
            __half2 h0 = __floats2half2_rn(v.x, v.y);
            __half2 h1 = __floats2half2_rn(v.z, v.w);
            uint32_t o = xsG + (uint32_t)(prow[j] * XS + pc4[j] * 4) * 2u;
            asm volatile("st.shared.v2.b32 [%0], {%1,%2};"
                         :: "r"(o), "r"(*(uint32_t*)&h0), "r"(*(uint32_t*)&h1) : "memory");
        }
        int myidx = 0;
        if (tg < 128) myidx = istRd[tg];

        // issue next tile's prefetch into the bytes this thread just consumed
        const int next = tile + stride2;
        if (next < NT) {
            const int r0n = next * TILE;
            #pragma unroll
            for (int j = 0; j < 4; ++j)
                CP_ASYNC16(xstG + (uint32_t)(prow[j] * 32 + pc4[j] * 4) * 4u,
                           &x[(size_t)(r0n + prow[j]) * 32 + pc4[j] * 4]);
            if (tg < 128) CP_ASYNC4(istG + (uint32_t)tg * 4u, &index[r0n + tg]);
        }
        CP_COMMIT();
        if (tg < 128) idxG[tg] = myidx;
        __syncwarp();

        layer_h16<2, XS, XS>(xsW, w1A, hb1, hW, lane);   // layer 1, K=32
        __syncwarp();
        layer_h16<8, HS, HS>(hW, w2A, hb2, hW, lane);    // layer 2, K=128
        __syncwarp();
        layer_f32<8, HS, HS>(hW, w3A, fb3, hW, lane);    // layer 3, K=128, f32 accum
        asm volatile("bar.sync %0, 256;" :: "r"(barid) : "memory");

        // sorted segment reduction over the group's 128 rows (fp16 h)
        {
            const int col  = tg & 127;
            const int half = tg >> 7;
            const int base = half * 64;
            float run = 0.0f;
            int cur = idxG[base];
            #pragma unroll 4
            for (int r = 0; r < 64; ++r) {
                int sg  = idxG[base + r];
                float v = __half2float(hRd[(base + r) * HS + col]);
                if (sg != cur) {
                    atomicAdd(&g_agg[cur * EMB + col], run);
                    run = 0.0f; cur = sg;
                }
                run += v;
            }
            atomicAdd(&g_agg[cur * EMB + col], run);
        }
        asm volatile("bar.sync %0, 256;" :: "r"(barid) : "memory");
    }
}

// ---------------------------------------------------------------------------
// Kernel 2: global MLP + log_softmax. Also re-zeroes its g_agg slice after
// reading it, so the next graph replay starts from a zeroed buffer (replaces
// the separate zero_agg launch; g_agg is zero-initialized at module load).
// ---------------------------------------------------------------------------
struct Smem2 {
    float W1[128 * 128];
    float W2[128 * 128];
    float W3[128 * 32];
    float b1[128], b2[128], b3[32];
    float B0[64 * HPAD];
    float B1[64 * HPAD];
    float sc[64 * 33];
};

template<int K, int SA, bool RELU>
__device__ __forceinline__ void gemm128(const float* __restrict__ A,
                                        const float* __restrict__ W,
                                        const float* __restrict__ bias,
                                        float* __restrict__ B,
                                        int rowg, int colg)
{
    float acc[4][8];
    {
        float4 bv0 = *(const float4*)&bias[colg * 8];
        float4 bv1 = *(const float4*)&bias[colg * 8 + 4];
        #pragma unroll
        for (int i = 0; i < 4; ++i) {
            acc[i][0] = bv0.x; acc[i][1] = bv0.y; acc[i][2] = bv0.z; acc[i][3] = bv0.w;
            acc[i][4] = bv1.x; acc[i][5] = bv1.y; acc[i][6] = bv1.z; acc[i][7] = bv1.w;
        }
    }
    #pragma unroll 2
    for (int k0 = 0; k0 < K; k0 += 4) {
        float a[4][4];
        #pragma unroll
        for (int i = 0; i < 4; ++i) {
            float4 v = *(const float4*)&A[(rowg * 4 + i) * SA + k0];
            a[i][0] = v.x; a[i][1] = v.y; a[i][2] = v.z; a[i][3] = v.w;
        }
        #pragma unroll
        for (int kk = 0; kk < 4; ++kk) {
            float4 w0 = *(const float4*)&W[(k0 + kk) * 128 + colg * 8];
            float4 w1 = *(const float4*)&W[(k0 + kk) * 128 + colg * 8 + 4];
            float wv[8] = {w0.x, w0.y, w0.z, w0.w, w1.x, w1.y, w1.z, w1.w};
            #pragma unroll
            for (int i = 0; i < 4; ++i)
                #pragma unroll
                for (int j = 0; j < 8; ++j)
                    acc[i][j] += a[i][kk] * wv[j];
        }
    }
    #pragma unroll
    for (int i = 0; i < 4; ++i) {
        float o[8];
        #pragma unroll
        for (int j = 0; j < 8; ++j)
            o[j] = RELU ? fmaxf(acc[i][j], 0.0f) : acc[i][j];
        float* dst = &B[(rowg * 4 + i) * HPAD + colg * 8];
        *(float4*)dst       = make_float4(o[0], o[1], o[2], o[3]);
        *(float4*)(dst + 4) = make_float4(o[4], o[5], o[6], o[7]);
    }
}

__global__ __launch_bounds__(256, 1)
void global_kernel(const float* __restrict__ gW1, const float* __restrict__ gb1,
                   const float* __restrict__ gW2, const float* __restrict__ gb2,
                   const float* __restrict__ gW3, const float* __restrict__ gb3,
                   float* __restrict__ out)
{
    extern __shared__ char raw[];
    Smem2& s = *reinterpret_cast<Smem2*>(raw);
    const int t = threadIdx.x;

    for (int i = t * 4; i < 128 * 128; i += 1024) *(float4*)&s.W1[i] = *(const float4*)&gW1[i];
    for (int i = t * 4; i < 128 * 128; i += 1024) *(float4*)&s.W2[i] = *(const float4*)&gW2[i];
    for (int i = t * 4; i < 128 * 32;  i += 1024) *(float4*)&s.W3[i] = *(const float4*)&gW3[i];
    if (t < 128) { s.b1[t] = gb1[t]; s.b2[t] = gb2[t]; }
    if (t < 32)  { s.b3[t] = gb3[t]; }

    const int seg0 = blockIdx.x * 64;

    // load agg slice into SMEM and re-zero it for the next replay
    const float4 zero4 = make_float4(0.f, 0.f, 0.f, 0.f);
    for (int i = t * 4; i < 64 * 128; i += 1024) {
        int row = i >> 7, c = i & 127;
        float4* src = (float4*)&g_agg[(seg0 + row) * EMB + c];
        float4 v = *src;
        *src = zero4;
        *(float4*)&s.B0[row * HPAD + c] = v;
    }
    __syncthreads();

    const int colg = t & 15;
    const int rowg = t >> 4;

    gemm128<128, HPAD, true>(s.B0, s.W1, s.b1, s.B1, rowg, colg);
    __syncthreads();
    gemm128<128, HPAD, true>(s.B1, s.W2, s.b2, s.B0, rowg, colg);
    __syncthreads();

    {
        const int rowg3 = t >> 3;
        const int colg3 = t & 7;
        float acc[2][4];
        {
            float4 bv = *(const float4*)&s.b3[colg3 * 4];
            #pragma unroll
            for (int i = 0; i < 2; ++i) {
                acc[i][0] = bv.x; acc[i][1] = bv.y; acc[i][2] = bv.z; acc[i][3] = bv.w;
            }
        }
        #pragma unroll 2
        for (int k0 = 0; k0 < 128; k0 += 4) {
            float a[2][4];
            #pragma unroll
            for (int i = 0; i < 2; ++i) {
                float4 v = *(const float4*)&s.B0[(rowg3 * 2 + i) * HPAD + k0];
                a[i][0] = v.x; a[i][1] = v.y; a[i][2] = v.z; a[i][3] = v.w;
            }
            #pragma unroll
            for (int kk = 0; kk < 4; ++kk) {
                float4 w = *(const float4*)&s.W3[(k0 + kk) * 32 + colg3 * 4];
                float wv[4] = {w.x, w.y, w.z, w.w};
                #pragma unroll
                for (int i = 0; i < 2; ++i)
                    #pragma unroll
                    for (int j = 0; j < 4; ++j)
                        acc[i][j] += a[i][kk] * wv[j];
            }
        }
        #pragma unroll
        for (int i = 0; i < 2; ++i)
            #pragma unroll
            for (int j = 0; j < 4; ++j)
                s.sc[(rowg3 * 2 + i) * 33 + colg3 * 4 + j] = acc[i][j];
    }
    __syncthreads();

    if (t < 64) {
        float v[32];
        float m = -INFINITY;
        #pragma unroll
        for (int c = 0; c < 32; ++c) { v[c] = s.sc[t * 33 + c]; m = fmaxf(m, v[c]); }
        float sum = 0.0f;
        #pragma unroll
        for (int c = 0; c < 32; ++c) sum += expf(v[c] - m);
        float lse = m + logf(sum);
        float* dst = &out[(size_t)(seg0 + t) * 32];
        #pragma unroll
        for (int c = 0; c < 32; ++c) dst[c] = v[c] - lse;
    }
}

// ---------------------------------------------------------------------------
// Launch (2 kernels only)
// ---------------------------------------------------------------------------
extern "C" void kernel_launch(void* const* d_in, const int* in_sizes, int n_in,
                              void* d_out, int out_size)
{
    const float* x     = (const float*)d_in[0];
    const int*   index = (const int*)d_in[1];
    const float* lW1 = (const float*)d_in[2];
    const float* lb1 = (const float*)d_in[3];
    const float* lW2 = (const float*)d_in[4];
    const float* lb2 = (const float*)d_in[5];
    const float* lW3 = (const float*)d_in[6];
    const float* lb3 = (const float*)d_in[7];
    const float* gW1 = (const float*)d_in[8];
    const float* gb1 = (const float*)d_in[9];
    const float* gW2 = (const float*)d_in[10];
    const float* gb2 = (const float*)d_in[11];
    const float* gW3 = (const float*)d_in[12];
    const float* gb3 = (const float*)d_in[13];
    float* out = (float*)d_out;

    cudaFuncSetAttribute((const void*)local_mma,
                         cudaFuncAttributeMaxDynamicSharedMemorySize, SM_SZ);
    cudaFuncSetAttribute((const void*)global_kernel,
                         cudaFuncAttributeMaxDynamicSharedMemorySize, (int)sizeof(Smem2));

    local_mma<<<148, 512, SM_SZ>>>(x, index, lW1, lb1, lW2, lb2, lW3, lb3);
    global_kernel<<<N_SEG / 64, 256, sizeof(Smem2)>>>(gW1, gb1, gW2, gb2, gW3, gb3, out);
}

// round 12
// speedup vs baseline: 1.0298x; 1.0298x over previous
#include <cuda_runtime.h>
#include <cuda_fp16.h>
#include <math.h>
#include <stdint.h>

// ---------------------------------------------------------------------------
// Problem constants
// ---------------------------------------------------------------------------
#define N_VOTERS   1048576
#define N_SEG      4096
#define EMB        128
#define TILE       128                     // voters per tile
#define NT         (N_VOTERS / TILE)       // 8192 tiles
#define XS         40                      // row stride (halves) for K=32 bufs
#define HS         136                     // row stride (halves) for K=128 bufs

// zero-initialized at module load; every execution re-zeroes it in global_mma
__device__ float g_agg[N_SEG * EMB];

// ---------------------------------------------------------------------------
// Local-kernel SMEM layout (byte offsets, 16B aligned). Two tile groups.
// ---------------------------------------------------------------------------
#define SM_W1    0        // [128][XS] half : 10240
#define SM_W2    10240    // [128][HS] half : 34816
#define SM_W3    45056    // [128][HS] half : 34816
#define SM_XS    79872    // 2 x [128][XS] half : 20480
#define SM_H     100352   // 2 x [128][HS] half : 69632
#define SM_B3    169984   // f32 bias3 : 512
#define SM_IDX   170496   // 2 x 128 int : 1024
#define SM_HB1   171520   // half2 bias1 : 256
#define SM_HB2   171776   // half2 bias2 : 256
#define SM_XST   172032   // 2 x [128][32] f32 x-stage : 32768
#define SM_IST   204800   // 2 x 128 int idx-stage : 1024
#define SM_SZ    205824

// ---------------------------------------------------------------------------
// Global-kernel SMEM layout
// ---------------------------------------------------------------------------
#define GS_W1    0        // [128][HS] half : 34816
#define GS_W2    34816    // [128][HS] half : 34816
#define GS_W3    69632    // [32][HS]  half : 8704
#define GS_H     78336    // [128][HS] half : 34816 (agg -> h1 -> h2 in place)
#define GS_SC    113152   // [128][34] f32 : 17408
#define GS_B1    130560   // f32 : 512
#define GS_B2    131072   // f32 : 512
#define GS_B3    131584   // f32 : 128
#define GS_SZ    131712

static __device__ __forceinline__ uint32_t s2u(const void* p) {
    uint32_t a;
    asm("{ .reg .u64 t; cvta.to.shared.u64 t, %1; cvt.u32.u64 %0, t; }" : "=r"(a) : "l"(p));
    return a;
}

static __device__ __forceinline__ void ldsm4(uint32_t* r, uint32_t addr) {
    asm volatile("ldmatrix.sync.aligned.m8n8.x4.shared.b16 {%0,%1,%2,%3}, [%4];"
                 : "=r"(r[0]), "=r"(r[1]), "=r"(r[2]), "=r"(r[3]) : "r"(addr));
}

static __device__ __forceinline__ void stsm4(uint32_t addr, uint32_t r0, uint32_t r1,
                                             uint32_t r2, uint32_t r3) {
    asm volatile("stmatrix.sync.aligned.m8n8.x4.shared.b16 [%0], {%1,%2,%3,%4};"
                 :: "r"(addr), "r"(r0), "r"(r1), "r"(r2), "r"(r3) : "memory");
}

static __device__ __forceinline__ void mma16816_f32(float* d, const uint32_t* a,
                                                    uint32_t b0, uint32_t b1) {
    asm volatile("mma.sync.aligned.m16n8k16.row.col.f32.f16.f16.f32 "
                 "{%0,%1,%2,%3}, {%4,%5,%6,%7}, {%8,%9}, {%0,%1,%2,%3};"
                 : "+f"(d[0]), "+f"(d[1]), "+f"(d[2]), "+f"(d[3])
                 : "r"(a[0]), "r"(a[1]), "r"(a[2]), "r"(a[3]), "r"(b0), "r"(b1));
}

static __device__ __forceinline__ void mma16816_f16(uint32_t* d, const uint32_t* a,
                                                    uint32_t b0, uint32_t b1) {
    asm volatile("mma.sync.aligned.m16n8k16.row.col.f16.f16.f16.f16 "
                 "{%0,%1}, {%2,%3,%4,%5}, {%6,%7}, {%0,%1};"
                 : "+r"(d[0]), "+r"(d[1])
                 : "r"(a[0]), "r"(a[1]), "r"(a[2]), "r"(a[3]), "r"(b0), "r"(b1));
}

#define CP_ASYNC16(dst, src) asm volatile("cp.async.cg.shared.global [%0], [%1], 16;" :: "r"(dst), "l"(src) : "memory")
#define CP_ASYNC4(dst, src)  asm volatile("cp.async.ca.shared.global [%0], [%1], 4;"  :: "r"(dst), "l"(src) : "memory")
#define CP_COMMIT()          asm volatile("cp.async.commit_group;" ::: "memory")
#define CP_WAIT0()           asm volatile("cp.async.wait_group 0;" ::: "memory")

// ---------------------------------------------------------------------------
// fp16-accumulating layer: ReLU, stmatrix out (stride HS)
// ---------------------------------------------------------------------------
template<int KCH, int STA, int STB>
static __device__ __forceinline__ void layer_h16(uint32_t aAddr, uint32_t bAddr,
                                                 const __half2* __restrict__ hbias,
                                                 uint32_t outAddr, int lane)
{
    const int l7 = lane & 7, lq = (lane >> 3) & 1, lh = lane >> 4;
    const uint32_t aRow = aAddr + (uint32_t)((l7 + lq * 8) * STA) * 2u + (uint32_t)lh * 16u;
    const uint32_t bRow = bAddr + (uint32_t)((l7 + lh * 8) * STB) * 2u + (uint32_t)lq * 16u;

    uint32_t d[16][2];
    #pragma unroll
    for (int n = 0; n < 16; ++n) { d[n][0] = 0u; d[n][1] = 0u; }

    #pragma unroll
    for (int kc = 0; kc < KCH; ++kc) {
        uint32_t a[4];
        ldsm4(a, aRow + (uint32_t)kc * 32u);
        #pragma unroll
        for (int p = 0; p < 8; ++p) {
            uint32_t b[4];
            ldsm4(b, bRow + (uint32_t)p * (32u * STB) + (uint32_t)kc * 32u);
            mma16816_f16(d[2 * p],     a, b[0], b[1]);
            mma16816_f16(d[2 * p + 1], a, b[2], b[3]);
        }
    }

    const int cq = 2 * (lane & 3);
    const __half2 z = __float2half2_rn(0.0f);
    const uint32_t stBase = outAddr + ((uint32_t)((lane & 15) * HS) + (uint32_t)((lane >> 4) * 8)) * 2u;
    #pragma unroll
    for (int p = 0; p < 8; ++p) {
        const int n0 = 2 * p, n1 = 2 * p + 1;
        __half2 hb0 = hbias[(n0 * 8 + cq) >> 1];
        __half2 hb1 = hbias[(n1 * 8 + cq) >> 1];
        __half2 v00 = __hmax2(__hadd2(*(__half2*)&d[n0][0], hb0), z);
        __half2 v01 = __hmax2(__hadd2(*(__half2*)&d[n0][1], hb0), z);
        __half2 v10 = __hmax2(__hadd2(*(__half2*)&d[n1][0], hb1), z);
        __half2 v11 = __hmax2(__hadd2(*(__half2*)&d[n1][1], hb1), z);
        stsm4(stBase + (uint32_t)p * 32u,
              *(uint32_t*)&v00, *(uint32_t*)&v01, *(uint32_t*)&v10, *(uint32_t*)&v11);
    }
}

// ---------------------------------------------------------------------------
// fp32-accumulating layer: optional ReLU, stmatrix fp16 out (stride HS)
// ---------------------------------------------------------------------------
template<int KCH, int STA, int STB, bool RELU>
static __device__ __forceinline__ void layer_f32(uint32_t aAddr, uint32_t bAddr,
                                                 const float* __restrict__ bias,
                                                 uint32_t outAddr, int lane)
{
    const int l7 = lane & 7, lq = (lane >> 3) & 1, lh = lane >> 4;
    const uint32_t aRow = aAddr + (uint32_t)((l7 + lq * 8) * STA) * 2u + (uint32_t)lh * 16u;
    const uint32_t bRow = bAddr + (uint32_t)((l7 + lh * 8) * STB) * 2u + (uint32_t)lq * 16u;

    float d[16][4];
    #pragma unroll
    for (int n = 0; n < 16; ++n)
        #pragma unroll
        for (int j = 0; j < 4; ++j) d[n][j] = 0.0f;

    #pragma unroll
    for (int kc = 0; kc < KCH; ++kc) {
        uint32_t a[4];
        ldsm4(a, aRow + (uint32_t)kc * 32u);
        #pragma unroll
        for (int p = 0; p < 8; ++p) {
            uint32_t b[4];
            ldsm4(b, bRow + (uint32_t)p * (32u * STB) + (uint32_t)kc * 32u);
            mma16816_f32(d[2 * p],     a, b[0], b[1]);
            mma16816_f32(d[2 * p + 1], a, b[2], b[3]);
        }
    }

    const int cq = 2 * (lane & 3);
    const uint32_t stBase = outAddr + ((uint32_t)((lane & 15) * HS) + (uint32_t)((lane >> 4) * 8)) * 2u;
    #pragma unroll
    for (int p = 0; p < 8; ++p) {
        const int n0 = 2 * p, n1 = 2 * p + 1;
        const int c0 = n0 * 8 + cq, c1 = n1 * 8 + cq;
        float a0 = d[n0][0] + bias[c0], a1 = d[n0][1] + bias[c0 + 1];
        float a2 = d[n0][2] + bias[c0], a3 = d[n0][3] + bias[c0 + 1];
        float b0 = d[n1][0] + bias[c1], b1 = d[n1][1] + bias[c1 + 1];
        float b2 = d[n1][2] + bias[c1], b3 = d[n1][3] + bias[c1 + 1];
        if (RELU) {
            a0 = fmaxf(a0, 0.f); a1 = fmaxf(a1, 0.f); a2 = fmaxf(a2, 0.f); a3 = fmaxf(a3, 0.f);
            b0 = fmaxf(b0, 0.f); b1 = fmaxf(b1, 0.f); b2 = fmaxf(b2, 0.f); b3 = fmaxf(b3, 0.f);
        }
        __half2 v00 = __floats2half2_rn(a0, a1);
        __half2 v01 = __floats2half2_rn(a2, a3);
        __half2 v10 = __floats2half2_rn(b0, b1);
        __half2 v11 = __floats2half2_rn(b2, b3);
        stsm4(stBase + (uint32_t)p * 32u,
              *(uint32_t*)&v00, *(uint32_t*)&v01, *(uint32_t*)&v10, *(uint32_t*)&v11);
    }
}

// ---------------------------------------------------------------------------
// Kernel 1: fp16 mma.sync local MLP + sorted segment-sum.
// 512 threads = two independent 8-warp tile groups; cp.async x/idx prefetch.
// ---------------------------------------------------------------------------
__global__ __launch_bounds__(512, 1)
void local_mma(const float* __restrict__ x,
               const int* __restrict__ index,
               const float* __restrict__ lW1, const float* __restrict__ lb1,
               const float* __restrict__ lW2, const float* __restrict__ lb2,
               const float* __restrict__ lW3, const float* __restrict__ lb3)
{
    extern __shared__ __align__(1024) char sm[];
    const uint32_t sb = s2u(sm);
    const int t    = threadIdx.x;
    const int lane = t & 31;
    const int g    = t >> 8;
    const int tg   = t & 255;
    const int wl   = (t >> 5) & 7;

    __half*  W1t = (__half*)(sm + SM_W1);
    __half*  W2t = (__half*)(sm + SM_W2);
    __half*  W3t = (__half*)(sm + SM_W3);
    float*   fb3 = (float*)(sm + SM_B3);
    __half2* hb1 = (__half2*)(sm + SM_HB1);
    __half2* hb2 = (__half2*)(sm + SM_HB2);

    for (int i = t; i < 32 * 128; i += 512) {
        int k = i >> 7, n = i & 127;
        W1t[n * XS + k] = __float2half_rn(lW1[i]);
    }
    for (int i = t; i < 128 * 128; i += 512) {
        int k = i >> 7, n = i & 127;
        W2t[n * HS + k] = __float2half_rn(lW2[i]);
        W3t[n * HS + k] = __float2half_rn(lW3[i]);
    }
    if (t < 128) fb3[t] = lb3[t];
    if (t < 64) {
        hb1[t] = __floats2half2_rn(lb1[2 * t], lb1[2 * t + 1]);
        hb2[t] = __floats2half2_rn(lb2[2 * t], lb2[2 * t + 1]);
    }
    __syncthreads();

    const uint32_t xsG  = sb + SM_XS  + (uint32_t)g * 10240u;
    const uint32_t hG   = sb + SM_H   + (uint32_t)g * 34816u;
    const uint32_t xstG = sb + SM_XST + (uint32_t)g * 16384u;
    const uint32_t istG = sb + SM_IST + (uint32_t)g * 512u;
    const uint32_t xsW  = xsG + (uint32_t)(16 * wl * XS) * 2u;
    const uint32_t hW   = hG  + (uint32_t)(16 * wl * HS) * 2u;
    const uint32_t w1A  = sb + SM_W1;
    const uint32_t w2A  = sb + SM_W2;
    const uint32_t w3A  = sb + SM_W3;
    int*          idxG  = (int*)(sm + SM_IDX + g * 512);
    const int*   istRd  = (const int*)(sm + SM_IST + g * 512);
    const float* xstRd  = (const float*)(sm + SM_XST + g * 16384);
    const __half* hRd   = (const __half*)(sm + (SM_H + g * 34816));
    const int    barid  = 1 + g;
    const int    stride2 = gridDim.x * 2;

    int prow[4], pc4[4];
    #pragma unroll
    for (int j = 0; j < 4; ++j) {
        int f = lane + 32 * j;
        prow[j] = 16 * wl + (f >> 3);
        pc4[j]  = f & 7;
    }

    int tile = blockIdx.x * 2 + g;

    if (tile < NT) {
        const int r0n = tile * TILE;
        #pragma unroll
        for (int j = 0; j < 4; ++j)
            CP_ASYNC16(xstG + (uint32_t)(prow[j] * 32 + pc4[j] * 4) * 4u,
                       &x[(size_t)(r0n + prow[j]) * 32 + pc4[j] * 4]);
        if (tg < 128) CP_ASYNC4(istG + (uint32_t)tg * 4u, &index[r0n + tg]);
    }
    CP_COMMIT();

    for (; tile < NT; tile += stride2) {
        CP_WAIT0();

        #pragma unroll
        for (int j = 0; j < 4; ++j) {
            float4 v = *(const float4*)&xstRd[prow[j] * 32 + pc4[j] * 4];
            __half2 h0 = __floats2half2_rn(v.x, v.y);
            __half2 h1 = __floats2half2_rn(v.z, v.w);
            uint32_t o = xsG + (uint32_t)(prow[j] * XS + pc4[j] * 4) * 2u;
            asm volatile("st.shared.v2.b32 [%0], {%1,%2};"
                         :: "r"(o), "r"(*(uint32_t*)&h0), "r"(*(uint32_t*)&h1) : "memory");
        }
        int myidx = 0;
        if (tg < 128) myidx = istRd[tg];

        const int next = tile + stride2;
        if (next < NT) {
            const int r0n = next * TILE;
            #pragma unroll
            for (int j = 0; j < 4; ++j)
                CP_ASYNC16(xstG + (uint32_t)(prow[j] * 32 + pc4[j] * 4) * 4u,
                           &x[(size_t)(r0n + prow[j]) * 32 + pc4[j] * 4]);
            if (tg < 128) CP_ASYNC4(istG + (uint32_t)tg * 4u, &index[r0n + tg]);
        }
        CP_COMMIT();
        if (tg < 128) idxG[tg] = myidx;
        __syncwarp();

        layer_h16<2, XS, XS>(xsW, w1A, hb1, hW, lane);          // layer 1, K=32
        __syncwarp();
        layer_h16<8, HS, HS>(hW, w2A, hb2, hW, lane);           // layer 2, K=128
        __syncwarp();
        layer_f32<8, HS, HS, false>(hW, w3A, fb3, hW, lane);    // layer 3, f32 accum
        asm volatile("bar.sync %0, 256;" :: "r"(barid) : "memory");

        {
            const int col  = tg & 127;
            const int half = tg >> 7;
            const int base = half * 64;
            float run = 0.0f;
            int cur = idxG[base];
            #pragma unroll 4
            for (int r = 0; r < 64; ++r) {
                int sg  = idxG[base + r];
                float v = __half2float(hRd[(base + r) * HS + col]);
                if (sg != cur) {
                    atomicAdd(&g_agg[cur * EMB + col], run);
                    run = 0.0f; cur = sg;
                }
                run += v;
            }
            atomicAdd(&g_agg[cur * EMB + col], run);
        }
        asm volatile("bar.sync %0, 256;" :: "r"(barid) : "memory");
    }
}

// ---------------------------------------------------------------------------
// Kernel 2: global MLP + log_softmax on tensor cores.
// 32 blocks x 8 warps; each block owns 128 segments; warp owns 16 rows.
// Re-zeroes its g_agg slice while reading it (replay invariant).
// ---------------------------------------------------------------------------
__global__ __launch_bounds__(256, 1)
void global_mma(const float* __restrict__ gW1, const float* __restrict__ gb1,
                const float* __restrict__ gW2, const float* __restrict__ gb2,
                const float* __restrict__ gW3, const float* __restrict__ gb3,
                float* __restrict__ out)
{
    extern __shared__ __align__(1024) char sm[];
    const uint32_t sb = s2u(sm);
    const int t    = threadIdx.x;
    const int lane = t & 31;
    const int wl   = t >> 5;          // warp 0..7

    __half* W1t = (__half*)(sm + GS_W1);
    __half* W2t = (__half*)(sm + GS_W2);
    __half* W3t = (__half*)(sm + GS_W3);
    float*  fb1 = (float*)(sm + GS_B1);
    float*  fb2 = (float*)(sm + GS_B2);
    float*  fb3 = (float*)(sm + GS_B3);
    float*  sc  = (float*)(sm + GS_SC);

    // convert weights to fp16 [n][k]
    for (int i = t; i < 128 * 128; i += 256) {
        int k = i >> 7, n = i & 127;
        W1t[n * HS + k] = __float2half_rn(gW1[i]);
        W2t[n * HS + k] = __float2half_rn(gW2[i]);
    }
    for (int i = t; i < 128 * 32; i += 256) {
        int k = i >> 5, n = i & 31;
        W3t[n * HS + k] = __float2half_rn(gW3[i]);
    }
    if (t < 128) { fb1[t] = gb1[t]; fb2[t] = gb2[t]; }
    if (t < 32)  fb3[t] = gb3[t];

    // load agg slice -> fp16 h (and re-zero g_agg for next replay)
    const int seg0 = blockIdx.x * 128;
    const float4 zero4 = make_float4(0.f, 0.f, 0.f, 0.f);
    for (int i = t * 4; i < 128 * 128; i += 1024) {
        int row = i >> 7, c = i & 127;
        float4* src = (float4*)&g_agg[(size_t)(seg0 + row) * EMB + c];
        float4 v = *src;
        *src = zero4;
        __half2 h0 = __floats2half2_rn(v.x, v.y);
        __half2 h1 = __floats2half2_rn(v.z, v.w);
        uint32_t o = sb + GS_H + (uint32_t)(row * HS + c) * 2u;
        asm volatile("st.shared.v2.b32 [%0], {%1,%2};"
                     :: "r"(o), "r"(*(uint32_t*)&h0), "r"(*(uint32_t*)&h1) : "memory");
    }
    __syncthreads();

    const uint32_t hW  = sb + GS_H + (uint32_t)(16 * wl * HS) * 2u;
    const uint32_t w1A = sb + GS_W1;
    const uint32_t w2A = sb + GS_W2;
    const uint32_t w3A = sb + GS_W3;

    layer_f32<8, HS, HS, true>(hW, w1A, fb1, hW, lane);   // layer 1: relu
    __syncwarp();
    layer_f32<8, HS, HS, true>(hW, w2A, fb2, hW, lane);   // layer 2: relu
    __syncwarp();

    // layer 3: N=32, f32 accum -> f32 scores (stride 34)
    {
        const int l7 = lane & 7, lq = (lane >> 3) & 1, lh = lane >> 4;
        const uint32_t aRow = hW + (uint32_t)((l7 + lq * 8) * HS) * 2u + (uint32_t)lh * 16u;
        const uint32_t bRow = w3A + (uint32_t)((l7 + lh * 8) * HS) * 2u + (uint32_t)lq * 16u;

        float d[4][4];
        #pragma unroll
        for (int n = 0; n < 4; ++n)
            #pragma unroll
            for (int j = 0; j < 4; ++j) d[n][j] = 0.0f;

        #pragma unroll
        for (int kc = 0; kc < 8; ++kc) {
            uint32_t a[4];
            ldsm4(a, aRow + (uint32_t)kc * 32u);
            #pragma unroll
            for (int p = 0; p < 2; ++p) {
                uint32_t b[4];
                ldsm4(b, bRow + (uint32_t)p * (32u * HS) + (uint32_t)kc * 32u);
                mma16816_f32(d[2 * p],     a, b[0], b[1]);
                mma16816_f32(d[2 * p + 1], a, b[2], b[3]);
            }
        }

        const int r = lane >> 2, cq = 2 * (lane & 3);
        float* scW = sc + 16 * wl * 34;
        #pragma unroll
        for (int n = 0; n < 4; ++n) {
            const int c0 = n * 8 + cq;
            float v0 = d[n][0] + fb3[c0], v1 = d[n][1] + fb3[c0 + 1];
            float v2 = d[n][2] + fb3[c0], v3 = d[n][3] + fb3[c0 + 1];
            *(float2*)&scW[r * 34 + c0]       = make_float2(v0, v1);
            *(float2*)&scW[(r + 8) * 34 + c0] = make_float2(v2, v3);
        }
    }
    __syncthreads();

    // log_softmax: thread r (< 128) handles row r
    if (t < 128) {
        float v[32];
        float m = -INFINITY;
        #pragma unroll
        for (int c = 0; c < 32; ++c) { v[c] = sc[t * 34 + c]; m = fmaxf(m, v[c]); }
        float sum = 0.0f;
        #pragma unroll
        for (int c = 0; c < 32; ++c) sum += expf(v[c] - m);
        float lse = m + logf(sum);
        float* dst = &out[(size_t)(seg0 + t) * 32];
        #pragma unroll
        for (int c = 0; c < 32; ++c) dst[c] = v[c] - lse;
    }
}

// ---------------------------------------------------------------------------
// Launch (2 kernels)
// ---------------------------------------------------------------------------
extern "C" void kernel_launch(void* const* d_in, const int* in_sizes, int n_in,
                              void* d_out, int out_size)
{
    const float* x     = (const float*)d_in[0];
    const int*   index = (const int*)d_in[1];
    const float* lW1 = (const float*)d_in[2];
    const float* lb1 = (const float*)d_in[3];
    const float* lW2 = (const float*)d_in[4];
    const float* lb2 = (const float*)d_in[5];
    const float* lW3 = (const float*)d_in[6];
    const float* lb3 = (const float*)d_in[7];
    const float* gW1 = (const float*)d_in[8];
    const float* gb1 = (const float*)d_in[9];
    const float* gW2 = (const float*)d_in[10];
    const float* gb2 = (const float*)d_in[11];
    const float* gW3 = (const float*)d_in[12];
    const float* gb3 = (const float*)d_in[13];
    float* out = (float*)d_out;

    cudaFuncSetAttribute((const void*)local_mma,
                         cudaFuncAttributeMaxDynamicSharedMemorySize, SM_SZ);
    cudaFuncSetAttribute((const void*)global_mma,
                         cudaFuncAttributeMaxDynamicSharedMemorySize, GS_SZ);

    local_mma<<<148, 512, SM_SZ>>>(x, index, lW1, lb1, lW2, lb2, lW3, lb3);
    global_mma<<<N_SEG / 128, 256, GS_SZ>>>(gW1, gb1, gW2, gb2, gW3, gb3, out);
}